// round 11
// baseline (speedup 1.0000x reference)
#include <cuda_runtime.h>

#define D    32
#define KN   26
#define CPW  4               // cells per warp
#define WPB  12              // warps per block
#define TPB  (WPB * 32)
#define NMAX 125000
#define XSTR 36

__device__ float g_msg[NMAX * D];   // tanh(state @ W_msg + b_msg)

__device__ __forceinline__ float tanh_fast(float x) {
    float y;
    asm("tanh.approx.f32 %0, %1;" : "=f"(y) : "f"(x));
    return y;
}

// ---------------------------------------------------------------------------
// Prepass: g_msg[cell] = tanh(states[cell] @ W_msg + b_msg)
// ---------------------------------------------------------------------------
__global__ __launch_bounds__(384) void msg_prepass(
    int n, const float* __restrict__ states,
    const float* __restrict__ W_msg, const float* __restrict__ b_msg)
{
    __shared__ float sx[12][4 * XSTR];
    const int lane = threadIdx.x & 31, warp = threadIdx.x >> 5;
    const int base = (blockIdx.x * 12 + warp) * 4;
    if (base >= n) return;

    float wm[D];
#pragma unroll
    for (int i = 0; i < D; i++) wm[i] = __ldg(W_msg + i * D + lane);
    const float bm = __ldg(b_msg + lane);

    float* xb = sx[warp];
#pragma unroll
    for (int c = 0; c < 4; c++) {
        int cell = base + c;
        xb[c * XSTR + lane] = (cell < n) ? states[cell * D + lane] : 0.f;
    }
    __syncwarp();
#pragma unroll
    for (int c = 0; c < 4; c++) {
        int cell = base + c;
        float m = bm;
#pragma unroll
        for (int i8 = 0; i8 < 8; i8++) {
            float4 xv = *reinterpret_cast<const float4*>(xb + c * XSTR + 4 * i8);
            m = fmaf(xv.x, wm[4 * i8 + 0], m);
            m = fmaf(xv.y, wm[4 * i8 + 1], m);
            m = fmaf(xv.z, wm[4 * i8 + 2], m);
            m = fmaf(xv.w, wm[4 * i8 + 3], m);
        }
        if (cell < n) g_msg[cell * D + lane] = tanh_fast(m);
    }
}

// ---------------------------------------------------------------------------
// Main: paired LDG.64/f32x2 gather (tiers inline), 48 warps/SM, branch-free
// ---------------------------------------------------------------------------
__global__ __launch_bounds__(TPB, 4) void moe_main(
    int n,
    const float* __restrict__ states,
    const int*   __restrict__ nbr,
    const int*   __restrict__ tiers,
    const float* __restrict__ W_loc,  const float* __restrict__ b_loc,
    const float* __restrict__ W_fun,  const float* __restrict__ b_fun,
    const float* __restrict__ W_cnf,  const float* __restrict__ b_cnf,
    const float* __restrict__ W_gate, const float* __restrict__ b_gate,
    float* __restrict__ out)
{
    extern __shared__ char smem[];
    float4* sWloc4 = reinterpret_cast<float4*>(smem);
    float4* sWfun4 = sWloc4 + 16 * 32;
    float4* sWcnf4 = sWfun4 + 16 * 32;
    float4* sInAll = sWcnf4 + 16 * 32;           // WPB*CPW*32 float4
    float4* sGate  = sInAll + WPB * CPW * D;     // WPB*CPW

    for (int e = threadIdx.x; e < 16 * 32; e += TPB) {
        int i = (e >> 5) * 4, j = e & 31;
        sWloc4[e] = make_float4(W_loc[i * 32 + j], W_loc[(i + 1) * 32 + j],
                                W_loc[(i + 2) * 32 + j], W_loc[(i + 3) * 32 + j]);
        sWfun4[e] = make_float4(W_fun[i * 32 + j], W_fun[(i + 1) * 32 + j],
                                W_fun[(i + 2) * 32 + j], W_fun[(i + 3) * 32 + j]);
        sWcnf4[e] = make_float4(W_cnf[i * 32 + j], W_cnf[(i + 1) * 32 + j],
                                W_cnf[(i + 2) * 32 + j], W_cnf[(i + 3) * 32 + j]);
    }
    __syncthreads();

    const int lane = threadIdx.x & 31, warp = threadIdx.x >> 5;
    const int base = (blockIdx.x * WPB + warp) * CPW;
    if (base >= n) return;
    const unsigned FULL = 0xffffffffu;

    const int  half = lane >> 4;           // which neighbor of the pair
    const int  sub8 = (lane & 15) * 8;     // byte offset within 128B row
    const char* sbase = (const char*)states;
    const char* mbase = (const char*)g_msg;

    float4* inb = sInAll + warp * (CPW * D);
    float4* gwp = sGate  + warp * CPW;

    float wg[4][3];
#pragma unroll
    for (int s = 0; s < 4; s++)
#pragma unroll
        for (int e = 0; e < 3; e++)
            wg[s][e] = __ldg(W_gate + (s * D + lane) * 3 + e);
    const float bg0 = __ldg(b_gate + 0), bg1 = __ldg(b_gate + 1), bg2 = __ldg(b_gate + 2);

    const int lnk = min(lane, KN - 1);     // lane clamp (branch-free)

    // ---- gather (paired LDG.64 + f32x2) + eager gate; cells clamped ----
#pragma unroll
    for (int c = 0; c < CPW; c++) {
        const int cellc = min(base + c, n - 1);

        const float cu = states[cellc * D + lane];
        const int idx  = __ldg(nbr   + cellc * KN + lnk);
        const int myt  = __ldg(tiers + cellc * KN + lnk);
        const int mypk = idx * 128 + myt;

        const unsigned m0 = __ballot_sync(FULL, myt == 0) & 0x3ffffffu;
        const unsigned m1 = __ballot_sync(FULL, myt == 1) & 0x3ffffffu;
        const int n0 = __popc(m0), n1 = __popc(m1);
        const int n2 = KN - n0 - n1;

        unsigned long long t2 = 0ull, a02 = 0ull, s012 = 0ull, fm2 = 0ull;
#pragma unroll
        for (int j = 0; j < 13; j++) {
            const int pkA = __shfl_sync(FULL, mypk, 2 * j);
            const int pkB = __shfl_sync(FULL, mypk, 2 * j + 1);
            const int pk  = half ? pkB : pkA;
            const int t   = pk & 3;
            const long off = (long)(pk & ~127) + sub8;
            const char* sa = sbase + off;
            const char* ma = mbase + off;
            asm("{\n\t"
                ".reg .pred p0, p01, p1;\n\t"
                ".reg .b64 v, mv;\n\t"
                "setp.eq.s32 p0, %4, 0;\n\t"
                "setp.le.s32 p01, %4, 1;\n\t"
                "setp.eq.s32 p1, %4, 1;\n\t"
                "ld.global.cg.b64 v, [%5];\n\t"
                "add.rn.f32x2 %0, %0, v;\n\t"
                "@p0 add.rn.f32x2 %1, %1, v;\n\t"
                "@p01 add.rn.f32x2 %2, %2, v;\n\t"
                "mov.b64 mv, 0;\n\t"
                "@p1 ld.global.cg.b64 mv, [%6];\n\t"
                "@p1 add.rn.f32x2 %3, %3, mv;\n\t"
                "}"
                : "+l"(t2), "+l"(a02), "+l"(s012), "+l"(fm2)
                : "r"(t), "l"(sa), "l"(ma));
        }

        // unpack packed accumulators
        float tl, th, a0l, a0h, sl, sh, fml, fmh;
        asm("mov.b64 {%0,%1}, %2;" : "=f"(tl),  "=f"(th)  : "l"(t2));
        asm("mov.b64 {%0,%1}, %2;" : "=f"(a0l), "=f"(a0h) : "l"(a02));
        asm("mov.b64 {%0,%1}, %2;" : "=f"(sl),  "=f"(sh)  : "l"(s012));
        asm("mov.b64 {%0,%1}, %2;" : "=f"(fml), "=f"(fmh) : "l"(fm2));

        // cross-half reduce (even/odd neighbors)
        tl  += __shfl_xor_sync(FULL, tl,  16);  th  += __shfl_xor_sync(FULL, th,  16);
        a0l += __shfl_xor_sync(FULL, a0l, 16);  a0h += __shfl_xor_sync(FULL, a0h, 16);
        sl  += __shfl_xor_sync(FULL, sl,  16);  sh  += __shfl_xor_sync(FULL, sh,  16);
        fml += __shfl_xor_sync(FULL, fml, 16);  fmh += __shfl_xor_sync(FULL, fmh, 16);

        // redistribute: lane d takes dim d from (src lane d>>1, lo/hi by d&1)
        const int srcl = lane >> 1;
        const bool odd = (lane & 1);
        const float tA = __shfl_sync(FULL, tl,  srcl), tB = __shfl_sync(FULL, th,  srcl);
        const float aA = __shfl_sync(FULL, a0l, srcl), aB = __shfl_sync(FULL, a0h, srcl);
        const float sA = __shfl_sync(FULL, sl,  srcl), sB = __shfl_sync(FULL, sh,  srcl);
        const float fA = __shfl_sync(FULL, fml, srcl), fB = __shfl_sync(FULL, fmh, srcl);
        const float tot = odd ? tB : tA;
        const float a0s = odd ? aB : aA;
        const float s01 = odd ? sB : sA;
        const float fms = odd ? fB : fA;

        const float a0 = __fdividef(a0s,       fmaxf((float)n0, 1.f));
        const float a1 = __fdividef(s01 - a0s, fmaxf((float)n1, 1.f));
        const float a2 = __fdividef(tot - s01, fmaxf((float)n2, 1.f));
        const float fm = __fdividef(fms,       fmaxf((float)n1, 1.f));

        inb[c * D + lane] = make_float4(cu, a0, fm, a2);

        // gate (eager; all inputs in regs)
        float p0 = cu * wg[0][0] + a0 * wg[1][0] + a1 * wg[2][0] + a2 * wg[3][0];
        float p1 = cu * wg[0][1] + a0 * wg[1][1] + a1 * wg[2][1] + a2 * wg[3][1];
        float p2 = cu * wg[0][2] + a0 * wg[1][2] + a1 * wg[2][2] + a2 * wg[3][2];
#pragma unroll
        for (int o = 16; o > 0; o >>= 1) {
            p0 += __shfl_xor_sync(FULL, p0, o);
            p1 += __shfl_xor_sync(FULL, p1, o);
            p2 += __shfl_xor_sync(FULL, p2, o);
        }
        if (lane == 0) {
            const float g0 = p0 + bg0, g1 = p1 + bg1, g2 = p2 + bg2;
            const float mx = fmaxf(g0, fmaxf(g1, g2));
            const float e0 = __expf(g0 - mx), e1 = __expf(g1 - mx), e2 = __expf(g2 - mx);
            const float inv = __fdividef(1.f, e0 + e1 + e2);
            gwp[c] = make_float4(e0 * inv, e1 * inv, e2 * inv, 0.f);
        }
    }
    __syncwarp();

    // ---- fused pass: loc, fun, CNF conditioning half (h2) ----
    float accL[CPW], accF[CPW], h2[CPW];
    {
        const float bl = __ldg(b_loc + lane);
        const float bf = __ldg(b_fun + lane);
        const float bc = __ldg(b_cnf + lane);
#pragma unroll
        for (int c = 0; c < CPW; c++) { accL[c] = bl; accF[c] = bf; h2[c] = bc; }
    }

#pragma unroll
    for (int i4 = 0; i4 < 8; i4++) {
        const float4 wlT = sWloc4[i4 * 32 + lane];
        const float4 wlB = sWloc4[(i4 + 8) * 32 + lane];
        const float4 wfT = sWfun4[i4 * 32 + lane];
        const float4 wfB = sWfun4[(i4 + 8) * 32 + lane];
        const float4 wcB = sWcnf4[(i4 + 8) * 32 + lane];
#pragma unroll
        for (int c = 0; c < CPW; c++) {
            const float4 x0 = inb[c * D + 4 * i4 + 0];
            const float4 x1 = inb[c * D + 4 * i4 + 1];
            const float4 x2 = inb[c * D + 4 * i4 + 2];
            const float4 x3 = inb[c * D + 4 * i4 + 3];
            accL[c] = fmaf(x0.x, wlT.x, fmaf(x0.y, wlB.x, accL[c]));
            accL[c] = fmaf(x1.x, wlT.y, fmaf(x1.y, wlB.y, accL[c]));
            accL[c] = fmaf(x2.x, wlT.z, fmaf(x2.y, wlB.z, accL[c]));
            accL[c] = fmaf(x3.x, wlT.w, fmaf(x3.y, wlB.w, accL[c]));
            accF[c] = fmaf(x0.x, wfT.x, fmaf(x0.z, wfB.x, accF[c]));
            accF[c] = fmaf(x1.x, wfT.y, fmaf(x1.z, wfB.y, accF[c]));
            accF[c] = fmaf(x2.x, wfT.z, fmaf(x2.z, wfB.z, accF[c]));
            accF[c] = fmaf(x3.x, wfT.w, fmaf(x3.z, wfB.w, accF[c]));
            h2[c]   = fmaf(x0.w, wcB.x, h2[c]);
            h2[c]   = fmaf(x1.w, wcB.y, h2[c]);
            h2[c]   = fmaf(x2.w, wcB.z, h2[c]);
            h2[c]   = fmaf(x3.w, wcB.w, h2[c]);
        }
    }

    // ---- partial combine, init CNF state ----
    float opart[CPW], gw2[CPW], x[CPW];
#pragma unroll
    for (int c = 0; c < CPW; c++) {
        const float4 gwv = gwp[c];
        opart[c] = gwv.x * tanh_fast(accL[c]) + gwv.y * tanh_fast(accF[c]);
        gw2[c]   = gwv.z;
        x[c]     = inb[c * D + lane].x;
    }
    __syncwarp();

    // ---- CNF: 3 Euler steps; x staged into the now-dead sIn region ----
    float* xxb = reinterpret_cast<float*>(inb);
#pragma unroll
    for (int s = 0; s < 3; s++) {
        __syncwarp();
#pragma unroll
        for (int c = 0; c < CPW; c++) xxb[c * XSTR + lane] = x[c];
        __syncwarp();
        float acc[CPW];
#pragma unroll
        for (int c = 0; c < CPW; c++) acc[c] = h2[c];
#pragma unroll
        for (int i4 = 0; i4 < 8; i4++) {
            const float4 w = sWcnf4[i4 * 32 + lane];
#pragma unroll
            for (int c = 0; c < CPW; c++) {
                const float4 xv = *reinterpret_cast<const float4*>(xxb + c * XSTR + 4 * i4);
                acc[c] = fmaf(xv.x, w.x, fmaf(xv.y, w.y, fmaf(xv.z, w.z, fmaf(xv.w, w.w, acc[c]))));
            }
        }
#pragma unroll
        for (int c = 0; c < CPW; c++)
            x[c] = fmaf(1.0f / 3.0f, tanh_fast(acc[c]), x[c]);
    }

    // ---- final combine + store (only real cells) ----
#pragma unroll
    for (int c = 0; c < CPW; c++) {
        const int cell = base + c;
        if (cell < n)
            out[cell * D + lane] = opart[c] + gw2[c] * x[c];
    }
}

extern "C" void kernel_launch(void* const* d_in, const int* in_sizes, int n_in,
                              void* d_out, int out_size) {
    const float* states = (const float*)d_in[0];
    const int*   nbr    = (const int*)  d_in[1];
    const int*   tiers  = (const int*)  d_in[2];
    const float* W_loc  = (const float*)d_in[3];
    const float* b_loc  = (const float*)d_in[4];
    const float* W_msg  = (const float*)d_in[5];
    const float* b_msg  = (const float*)d_in[6];
    const float* W_fun  = (const float*)d_in[7];
    const float* b_fun  = (const float*)d_in[8];
    const float* W_cnf  = (const float*)d_in[9];
    const float* b_cnf  = (const float*)d_in[10];
    const float* W_gate = (const float*)d_in[11];
    const float* b_gate = (const float*)d_in[12];
    float* out = (float*)d_out;

    const int n = in_sizes[0] / D;
    const int blocksP = (n + 12 * 4 - 1) / (12 * 4);
    const int blocks  = (n + WPB * CPW - 1) / (WPB * CPW);

    // smem: weights 24 KB + sIn 24 KB + sGate 0.75 KB = 48.75 KB -> 4 blocks/SM
    const int smem_bytes = (3 * 16 * 32) * (int)sizeof(float4)
                         + (WPB * CPW * D) * (int)sizeof(float4)
                         + (WPB * CPW) * (int)sizeof(float4);
    static bool attr_set = false;
    if (!attr_set) {
        cudaFuncSetAttribute(moe_main, cudaFuncAttributeMaxDynamicSharedMemorySize, smem_bytes);
        attr_set = true;
    }

    msg_prepass<<<blocksP, 384>>>(n, states, W_msg, b_msg);
    moe_main<<<blocks, TPB, smem_bytes>>>(n, states, nbr, tiers,
                                          W_loc, b_loc, W_fun, b_fun,
                                          W_cnf, b_cnf, W_gate, b_gate, out);
}

// round 12
// speedup vs baseline: 1.1299x; 1.1299x over previous
#include <cuda_runtime.h>

#define D    32
#define KN   26
#define CPW  4               // cells per warp
#define WPB  12              // warps per block
#define TPB  (WPB * 32)
#define NMAX 125000
#define XSTR 36

__device__ float g_msg[NMAX * D];   // tanh(state @ W_msg + b_msg)

__device__ __forceinline__ float tanh_fast(float x) {
    float y;
    asm("tanh.approx.f32 %0, %1;" : "=f"(y) : "f"(x));
    return y;
}

// ---------------------------------------------------------------------------
// Prepass: g_msg[cell] = tanh(states[cell] @ W_msg + b_msg)
// ---------------------------------------------------------------------------
__global__ __launch_bounds__(384) void msg_prepass(
    int n, const float* __restrict__ states,
    const float* __restrict__ W_msg, const float* __restrict__ b_msg)
{
    __shared__ float sx[12][4 * XSTR];
    const int lane = threadIdx.x & 31, warp = threadIdx.x >> 5;
    const int base = (blockIdx.x * 12 + warp) * 4;
    if (base >= n) return;

    float wm[D];
#pragma unroll
    for (int i = 0; i < D; i++) wm[i] = __ldg(W_msg + i * D + lane);
    const float bm = __ldg(b_msg + lane);

    float* xb = sx[warp];
#pragma unroll
    for (int c = 0; c < 4; c++) {
        int cell = base + c;
        xb[c * XSTR + lane] = (cell < n) ? states[cell * D + lane] : 0.f;
    }
    __syncwarp();
#pragma unroll
    for (int c = 0; c < 4; c++) {
        int cell = base + c;
        float m = bm;
#pragma unroll
        for (int i8 = 0; i8 < 8; i8++) {
            float4 xv = *reinterpret_cast<const float4*>(xb + c * XSTR + 4 * i8);
            m = fmaf(xv.x, wm[4 * i8 + 0], m);
            m = fmaf(xv.y, wm[4 * i8 + 1], m);
            m = fmaf(xv.z, wm[4 * i8 + 2], m);
            m = fmaf(xv.w, wm[4 * i8 + 3], m);
        }
        if (cell < n) g_msg[cell * D + lane] = tanh_fast(m);
    }
}

// ---------------------------------------------------------------------------
// Main: paired LDG.64 gather (loads in C, 1-instr f32x2 asm adds), 48 warps/SM
// ---------------------------------------------------------------------------
__global__ __launch_bounds__(TPB, 4) void moe_main(
    int n,
    const float* __restrict__ states,
    const int*   __restrict__ nbr,
    const int*   __restrict__ tiers,
    const float* __restrict__ W_loc,  const float* __restrict__ b_loc,
    const float* __restrict__ W_fun,  const float* __restrict__ b_fun,
    const float* __restrict__ W_cnf,  const float* __restrict__ b_cnf,
    const float* __restrict__ W_gate, const float* __restrict__ b_gate,
    float* __restrict__ out)
{
    extern __shared__ char smem[];
    float4* sWloc4 = reinterpret_cast<float4*>(smem);
    float4* sWfun4 = sWloc4 + 16 * 32;
    float4* sWcnf4 = sWfun4 + 16 * 32;
    float4* sInAll = sWcnf4 + 16 * 32;           // WPB*CPW*32 float4
    float4* sGate  = sInAll + WPB * CPW * D;     // WPB*CPW

    for (int e = threadIdx.x; e < 16 * 32; e += TPB) {
        int i = (e >> 5) * 4, j = e & 31;
        sWloc4[e] = make_float4(W_loc[i * 32 + j], W_loc[(i + 1) * 32 + j],
                                W_loc[(i + 2) * 32 + j], W_loc[(i + 3) * 32 + j]);
        sWfun4[e] = make_float4(W_fun[i * 32 + j], W_fun[(i + 1) * 32 + j],
                                W_fun[(i + 2) * 32 + j], W_fun[(i + 3) * 32 + j]);
        sWcnf4[e] = make_float4(W_cnf[i * 32 + j], W_cnf[(i + 1) * 32 + j],
                                W_cnf[(i + 2) * 32 + j], W_cnf[(i + 3) * 32 + j]);
    }
    __syncthreads();

    const int lane = threadIdx.x & 31, warp = threadIdx.x >> 5;
    const int base = (blockIdx.x * WPB + warp) * CPW;
    if (base >= n) return;
    const unsigned FULL = 0xffffffffu;

    const int  half = lane >> 4;           // which neighbor of the pair
    const int  sub8 = (lane & 15) * 8;     // byte offset within 128B row
    const char* sbase = (const char*)states;
    const char* mbase = (const char*)g_msg;

    float4* inb = sInAll + warp * (CPW * D);
    float4* gwp = sGate  + warp * CPW;

    float wg[4][3];
#pragma unroll
    for (int s = 0; s < 4; s++)
#pragma unroll
        for (int e = 0; e < 3; e++)
            wg[s][e] = __ldg(W_gate + (s * D + lane) * 3 + e);
    const float bg0 = __ldg(b_gate + 0), bg1 = __ldg(b_gate + 1), bg2 = __ldg(b_gate + 2);

    const int lnk = min(lane, KN - 1);     // lane clamp (branch-free)

    // ---- gather: paired LDG.64 (C-level loads) + f32x2 asm accumulates ----
#pragma unroll
    for (int c = 0; c < CPW; c++) {
        const int cellc = min(base + c, n - 1);

        const float cu = states[cellc * D + lane];
        const int idx  = __ldg(nbr   + cellc * KN + lnk);
        const int myt  = __ldg(tiers + cellc * KN + lnk);
        const int mypk = idx * 128 + myt;

        const unsigned m0 = __ballot_sync(FULL, myt == 0) & 0x3ffffffu;
        const unsigned m1 = __ballot_sync(FULL, myt == 1) & 0x3ffffffu;
        const int n0 = __popc(m0), n1 = __popc(m1);
        const int n2 = KN - n0 - n1;

        unsigned long long t2 = 0ull, a02 = 0ull, s012 = 0ull, fm2 = 0ull;
#pragma unroll
        for (int j = 0; j < 13; j++) {
            const int pkA = __shfl_sync(FULL, mypk, 2 * j);
            const int pkB = __shfl_sync(FULL, mypk, 2 * j + 1);
            const int pk  = half ? pkB : pkA;
            const int t   = pk & 3;
            const long off = (long)(pk & ~127) + sub8;

            // state load: plain C -> ptxas batches all 13 (MLP preserved)
            const float2 v2 = __ldcg(reinterpret_cast<const float2*>(sbase + off));
            unsigned long long v;
            asm("mov.b64 %0, {%1, %2};" : "=l"(v) : "f"(v2.x), "f"(v2.y));

            // register-only accumulates (1-2 instr each)
            asm("add.rn.f32x2 %0, %0, %1;" : "+l"(t2) : "l"(v));
            asm("{.reg .pred p; setp.eq.s32 p, %2, 0; @p add.rn.f32x2 %0, %0, %1;}"
                : "+l"(a02) : "l"(v), "r"(t));
            asm("{.reg .pred p; setp.le.s32 p, %2, 1; @p add.rn.f32x2 %0, %0, %1;}"
                : "+l"(s012) : "l"(v), "r"(t));

            // msg: load-only predicated asm (independent output -> batchable)
            unsigned long long mv;
            asm("{.reg .pred p; setp.eq.s32 p, %2, 1; mov.b64 %0, 0; @p ld.global.cg.b64 %0, [%1];}"
                : "=l"(mv) : "l"(mbase + off), "r"(t));
            asm("add.rn.f32x2 %0, %0, %1;" : "+l"(fm2) : "l"(mv));
        }

        // unpack packed accumulators
        float tl, th, a0l, a0h, sl, sh, fml, fmh;
        asm("mov.b64 {%0,%1}, %2;" : "=f"(tl),  "=f"(th)  : "l"(t2));
        asm("mov.b64 {%0,%1}, %2;" : "=f"(a0l), "=f"(a0h) : "l"(a02));
        asm("mov.b64 {%0,%1}, %2;" : "=f"(sl),  "=f"(sh)  : "l"(s012));
        asm("mov.b64 {%0,%1}, %2;" : "=f"(fml), "=f"(fmh) : "l"(fm2));

        // cross-half reduce (even/odd neighbors)
        tl  += __shfl_xor_sync(FULL, tl,  16);  th  += __shfl_xor_sync(FULL, th,  16);
        a0l += __shfl_xor_sync(FULL, a0l, 16);  a0h += __shfl_xor_sync(FULL, a0h, 16);
        sl  += __shfl_xor_sync(FULL, sl,  16);  sh  += __shfl_xor_sync(FULL, sh,  16);
        fml += __shfl_xor_sync(FULL, fml, 16);  fmh += __shfl_xor_sync(FULL, fmh, 16);

        // redistribute: lane d takes dim d from (src lane d>>1, lo/hi by d&1)
        const int srcl = lane >> 1;
        const bool odd = (lane & 1);
        const float tA = __shfl_sync(FULL, tl,  srcl), tB = __shfl_sync(FULL, th,  srcl);
        const float aA = __shfl_sync(FULL, a0l, srcl), aB = __shfl_sync(FULL, a0h, srcl);
        const float sA = __shfl_sync(FULL, sl,  srcl), sB = __shfl_sync(FULL, sh,  srcl);
        const float fA = __shfl_sync(FULL, fml, srcl), fB = __shfl_sync(FULL, fmh, srcl);
        const float tot = odd ? tB : tA;
        const float a0s = odd ? aB : aA;
        const float s01 = odd ? sB : sA;
        const float fms = odd ? fB : fA;

        const float a0 = __fdividef(a0s,       fmaxf((float)n0, 1.f));
        const float a1 = __fdividef(s01 - a0s, fmaxf((float)n1, 1.f));
        const float a2 = __fdividef(tot - s01, fmaxf((float)n2, 1.f));
        const float fm = __fdividef(fms,       fmaxf((float)n1, 1.f));

        inb[c * D + lane] = make_float4(cu, a0, fm, a2);

        // gate (eager; all inputs in regs)
        float p0 = cu * wg[0][0] + a0 * wg[1][0] + a1 * wg[2][0] + a2 * wg[3][0];
        float p1 = cu * wg[0][1] + a0 * wg[1][1] + a1 * wg[2][1] + a2 * wg[3][1];
        float p2 = cu * wg[0][2] + a0 * wg[1][2] + a1 * wg[2][2] + a2 * wg[3][2];
#pragma unroll
        for (int o = 16; o > 0; o >>= 1) {
            p0 += __shfl_xor_sync(FULL, p0, o);
            p1 += __shfl_xor_sync(FULL, p1, o);
            p2 += __shfl_xor_sync(FULL, p2, o);
        }
        if (lane == 0) {
            const float g0 = p0 + bg0, g1 = p1 + bg1, g2 = p2 + bg2;
            const float mx = fmaxf(g0, fmaxf(g1, g2));
            const float e0 = __expf(g0 - mx), e1 = __expf(g1 - mx), e2 = __expf(g2 - mx);
            const float inv = __fdividef(1.f, e0 + e1 + e2);
            gwp[c] = make_float4(e0 * inv, e1 * inv, e2 * inv, 0.f);
        }
    }
    __syncwarp();

    // ---- fused pass: loc, fun, CNF conditioning half (h2) ----
    float accL[CPW], accF[CPW], h2[CPW];
    {
        const float bl = __ldg(b_loc + lane);
        const float bf = __ldg(b_fun + lane);
        const float bc = __ldg(b_cnf + lane);
#pragma unroll
        for (int c = 0; c < CPW; c++) { accL[c] = bl; accF[c] = bf; h2[c] = bc; }
    }

#pragma unroll
    for (int i4 = 0; i4 < 8; i4++) {
        const float4 wlT = sWloc4[i4 * 32 + lane];
        const float4 wlB = sWloc4[(i4 + 8) * 32 + lane];
        const float4 wfT = sWfun4[i4 * 32 + lane];
        const float4 wfB = sWfun4[(i4 + 8) * 32 + lane];
        const float4 wcB = sWcnf4[(i4 + 8) * 32 + lane];
#pragma unroll
        for (int c = 0; c < CPW; c++) {
            const float4 x0 = inb[c * D + 4 * i4 + 0];
            const float4 x1 = inb[c * D + 4 * i4 + 1];
            const float4 x2 = inb[c * D + 4 * i4 + 2];
            const float4 x3 = inb[c * D + 4 * i4 + 3];
            accL[c] = fmaf(x0.x, wlT.x, fmaf(x0.y, wlB.x, accL[c]));
            accL[c] = fmaf(x1.x, wlT.y, fmaf(x1.y, wlB.y, accL[c]));
            accL[c] = fmaf(x2.x, wlT.z, fmaf(x2.y, wlB.z, accL[c]));
            accL[c] = fmaf(x3.x, wlT.w, fmaf(x3.y, wlB.w, accL[c]));
            accF[c] = fmaf(x0.x, wfT.x, fmaf(x0.z, wfB.x, accF[c]));
            accF[c] = fmaf(x1.x, wfT.y, fmaf(x1.z, wfB.y, accF[c]));
            accF[c] = fmaf(x2.x, wfT.z, fmaf(x2.z, wfB.z, accF[c]));
            accF[c] = fmaf(x3.x, wfT.w, fmaf(x3.z, wfB.w, accF[c]));
            h2[c]   = fmaf(x0.w, wcB.x, h2[c]);
            h2[c]   = fmaf(x1.w, wcB.y, h2[c]);
            h2[c]   = fmaf(x2.w, wcB.z, h2[c]);
            h2[c]   = fmaf(x3.w, wcB.w, h2[c]);
        }
    }

    // ---- partial combine, init CNF state ----
    float opart[CPW], gw2[CPW], x[CPW];
#pragma unroll
    for (int c = 0; c < CPW; c++) {
        const float4 gwv = gwp[c];
        opart[c] = gwv.x * tanh_fast(accL[c]) + gwv.y * tanh_fast(accF[c]);
        gw2[c]   = gwv.z;
        x[c]     = inb[c * D + lane].x;
    }
    __syncwarp();

    // ---- CNF: 3 Euler steps; x staged into the now-dead sIn region ----
    float* xxb = reinterpret_cast<float*>(inb);
#pragma unroll
    for (int s = 0; s < 3; s++) {
        __syncwarp();
#pragma unroll
        for (int c = 0; c < CPW; c++) xxb[c * XSTR + lane] = x[c];
        __syncwarp();
        float acc[CPW];
#pragma unroll
        for (int c = 0; c < CPW; c++) acc[c] = h2[c];
#pragma unroll
        for (int i4 = 0; i4 < 8; i4++) {
            const float4 w = sWcnf4[i4 * 32 + lane];
#pragma unroll
            for (int c = 0; c < CPW; c++) {
                const float4 xv = *reinterpret_cast<const float4*>(xxb + c * XSTR + 4 * i4);
                acc[c] = fmaf(xv.x, w.x, fmaf(xv.y, w.y, fmaf(xv.z, w.z, fmaf(xv.w, w.w, acc[c]))));
            }
        }
#pragma unroll
        for (int c = 0; c < CPW; c++)
            x[c] = fmaf(1.0f / 3.0f, tanh_fast(acc[c]), x[c]);
    }

    // ---- final combine + store (only real cells) ----
#pragma unroll
    for (int c = 0; c < CPW; c++) {
        const int cell = base + c;
        if (cell < n)
            out[cell * D + lane] = opart[c] + gw2[c] * x[c];
    }
}

extern "C" void kernel_launch(void* const* d_in, const int* in_sizes, int n_in,
                              void* d_out, int out_size) {
    const float* states = (const float*)d_in[0];
    const int*   nbr    = (const int*)  d_in[1];
    const int*   tiers  = (const int*)  d_in[2];
    const float* W_loc  = (const float*)d_in[3];
    const float* b_loc  = (const float*)d_in[4];
    const float* W_msg  = (const float*)d_in[5];
    const float* b_msg  = (const float*)d_in[6];
    const float* W_fun  = (const float*)d_in[7];
    const float* b_fun  = (const float*)d_in[8];
    const float* W_cnf  = (const float*)d_in[9];
    const float* b_cnf  = (const float*)d_in[10];
    const float* W_gate = (const float*)d_in[11];
    const float* b_gate = (const float*)d_in[12];
    float* out = (float*)d_out;

    const int n = in_sizes[0] / D;
    const int blocksP = (n + 12 * 4 - 1) / (12 * 4);
    const int blocks  = (n + WPB * CPW - 1) / (WPB * CPW);

    const int smem_bytes = (3 * 16 * 32) * (int)sizeof(float4)
                         + (WPB * CPW * D) * (int)sizeof(float4)
                         + (WPB * CPW) * (int)sizeof(float4);
    static bool attr_set = false;
    if (!attr_set) {
        cudaFuncSetAttribute(moe_main, cudaFuncAttributeMaxDynamicSharedMemorySize, smem_bytes);
        attr_set = true;
    }

    msg_prepass<<<blocksP, 384>>>(n, states, W_msg, b_msg);
    moe_main<<<blocks, TPB, smem_bytes>>>(n, states, nbr, tiers,
                                          W_loc, b_loc, W_fun, b_fun,
                                          W_cnf, b_cnf, W_gate, b_gate, out);
}